// round 1
// baseline (speedup 1.0000x reference)
#include <cuda_runtime.h>

#define N_PATHS 1000000
#define N_LINKS 50000
#define K_HOPS  8

// Scratch: __device__ globals (no runtime allocation allowed).
__device__ float g_T[N_LINKS];
__device__ float g_bp[N_LINKS];
__device__ float g_rho[N_LINKS];
__device__ float g_Xl[N_LINKS];

__global__ void init_kernel() {
    int l = blockIdx.x * blockDim.x + threadIdx.x;
    if (l < N_LINKS) {
        g_T[l]  = 0.0f;
        g_bp[l] = 0.5f;
    }
}

// One pass of update_traffic: each thread walks 4 paths through their 8 hops.
// T[e] += t (RED, no return), then t *= (1 - bp[e]).
__global__ void traffic_kernel(const float* __restrict__ P,
                               const int*   __restrict__ edges) {
    int p0 = (blockIdx.x * blockDim.x + threadIdx.x) * 4;
    if (p0 >= N_PATHS) return;

    // A = P[:,1]; P is (N_PATHS, 3) row-major.
    float t0 = __ldg(&P[3 * p0 + 1]);
    float t1 = __ldg(&P[3 * p0 + 4]);
    float t2 = __ldg(&P[3 * p0 + 7]);
    float t3 = __ldg(&P[3 * p0 + 10]);

#pragma unroll
    for (int k = 0; k < K_HOPS; k++) {
        int4 e4 = *reinterpret_cast<const int4*>(edges + (size_t)k * N_PATHS + p0);
        int e0 = e4.x - N_PATHS;
        int e1 = e4.y - N_PATHS;
        int e2 = e4.z - N_PATHS;
        int e3 = e4.w - N_PATHS;

        atomicAdd(&g_T[e0], t0);
        atomicAdd(&g_T[e1], t1);
        atomicAdd(&g_T[e2], t2);
        atomicAdd(&g_T[e3], t3);

        t0 *= 1.0f - __ldg(&g_bp[e0]);
        t1 *= 1.0f - __ldg(&g_bp[e1]);
        t2 *= 1.0f - __ldg(&g_bp[e2]);
        t3 *= 1.0f - __ldg(&g_bp[e3]);
    }
}

// rho = T/cap ; bp = (1-rho)*rho^32 / (1 - rho^33 + 1e-8). Also re-zero T for next pass.
__global__ void link_update_kernel(const float* __restrict__ L) {
    int l = blockIdx.x * blockDim.x + threadIdx.x;
    if (l >= N_LINKS) return;

    float Tl = g_T[l];
    g_T[l] = 0.0f;

    float cap = __ldg(&L[l]) / 1000.0f;
    float rho = Tl / cap;

    float r2  = rho * rho;
    float r4  = r2 * r2;
    float r8  = r4 * r4;
    float r16 = r8 * r8;
    float r32 = r16 * r16;

    float denom = 1.0f - r32 * rho + 1e-8f;
    g_bp[l]  = (1.0f - rho) * r32 / denom;
    g_rho[l] = rho;
}

// Final per-link outputs: Lq, rho, pi0_final stacked, plus X_l for the path pass.
__global__ void final_link_kernel(const float* __restrict__ L,
                                  float* __restrict__ out) {
    int l = blockIdx.x * blockDim.x + threadIdx.x;
    if (l >= N_LINKS) return;

    float rho = g_rho[l];
    float r2  = rho * rho;
    float r4  = r2 * r2;
    float r8  = r4 * r4;
    float r16 = r8 * r8;
    float r32 = r16 * r16;
    float r33 = r32 * rho;

    float pi0 = (1.0f - rho) / (1.0f - r33);

    // s = sum_{m=0..32} coeff(m) * rho^m, coeff(0)=1, coeff(m)=m for m>=1
    float s  = 1.0f;
    float pw = 1.0f;
#pragma unroll
    for (int m = 1; m <= 32; m++) {
        pw *= rho;
        s  += (float)m * pw;
    }

    float Lq   = pi0 * s / 32.0f;
    float pi0f = pi0 * r32;
    float Xl   = Lq * 32000.0f / __ldg(&L[l]);

    g_Xl[l] = Xl;

    out[N_PATHS + 3 * l + 0] = Lq;
    out[N_PATHS + 3 * l + 1] = rho;
    out[N_PATHS + 3 * l + 2] = pi0f;
}

// res[p] = sum_k X_l[e[k,p]]   (pl_paths is identity -> plain gather-sum per path)
__global__ void final_path_kernel(const int* __restrict__ edges,
                                  float* __restrict__ out) {
    int p0 = (blockIdx.x * blockDim.x + threadIdx.x) * 4;
    if (p0 >= N_PATHS) return;

    float s0 = 0.0f, s1 = 0.0f, s2 = 0.0f, s3 = 0.0f;
#pragma unroll
    for (int k = 0; k < K_HOPS; k++) {
        int4 e4 = *reinterpret_cast<const int4*>(edges + (size_t)k * N_PATHS + p0);
        s0 += __ldg(&g_Xl[e4.x - N_PATHS]);
        s1 += __ldg(&g_Xl[e4.y - N_PATHS]);
        s2 += __ldg(&g_Xl[e4.z - N_PATHS]);
        s3 += __ldg(&g_Xl[e4.w - N_PATHS]);
    }
    out[p0 + 0] = s0;
    out[p0 + 1] = s1;
    out[p0 + 2] = s2;
    out[p0 + 3] = s3;
}

extern "C" void kernel_launch(void* const* d_in, const int* in_sizes, int n_in,
                              void* d_out, int out_size) {
    const float* P     = (const float*)d_in[0];   // (N_PATHS, 3)
    const float* L     = (const float*)d_in[1];   // (N_LINKS, 1)
    // d_in[2] = pl_paths: identity, unused
    const int*   edges = (const int*)d_in[3];     // (K_HOPS, N_PATHS)
    float* out = (float*)d_out;

    const int LB = (N_LINKS + 255) / 256;
    const int PB = (N_PATHS / 4 + 255) / 256;

    init_kernel<<<LB, 256>>>();
    for (int it = 0; it < 3; it++) {
        traffic_kernel<<<PB, 256>>>(P, edges);
        link_update_kernel<<<LB, 256>>>(L);
    }
    final_link_kernel<<<LB, 256>>>(L, out);
    final_path_kernel<<<PB, 256>>>(edges, out);
}